// round 13
// baseline (speedup 1.0000x reference)
#include <cuda_runtime.h>
#include <cuda_bf16.h>
#include <math.h>
#include <stdint.h>

#define BB    4
#define NPTS  2048
#define DD    128
#define KNB   32
#define MD    64
#define H1P   576      // padded hidden-1 (real 530)
#define H1W   288      // packed words per row
#define H1R   530
#define NNODES (BB*NPTS)        // 8192
#define NEDGES (NNODES*KNB)     // 262144

// ---------------- device scratch (no allocations allowed) ----------------
__device__ int   g_idx [NEDGES];
__device__ float g_relc[NEDGES*3];
__device__ float g_reld[NEDGES];
__device__ uint32_t g_Pb[(size_t)NNODES*H1W];   // bf16x2 packed P
__device__ uint32_t g_Qb[(size_t)NNODES*H1W];   // bf16x2 packed Q
__device__ float g_mi  [(size_t)NNODES*MD];
__device__ uint32_t g_We2T[64*288];    // bf16x2: {We2[2k][n], We2[2k+1][n]}
__device__ uint32_t g_Wc1T[256*32];    // bf16x2: {Wc1[2k][n], Wc1[2k+1][n]}
__device__ uint32_t g_We1Ta[576*64];   // bf16x2 We1^T rows 0..127
__device__ uint32_t g_We1Tb[576*64];   // rows 128..255
__device__ uint32_t g_RWb[9*288];      // packed fourier rows of We1 (256..264)
__device__ uint32_t g_B1b[288];        // packed be1

// FMA-only silu (fp32)
__device__ __forceinline__ float silu_p(float x){
    float t = fminf(fmaxf(x, -2.f), 2.f);
    float u = t*t;
    float p = fmaf(u, -2.10813e-4f, 2.0833333e-3f);
    p = fmaf(u, p, -2.0833333e-2f);
    p = fmaf(u, p, 2.5e-1f);
    return x * fmaf(t, p, 0.5f);
}
// Packed bf16x2 silu
__device__ __forceinline__ uint32_t silu2(__nv_bfloat162 x){
    __nv_bfloat162 hi = __float2bfloat162_rn(2.f);
    __nv_bfloat162 lo = __float2bfloat162_rn(-2.f);
    __nv_bfloat162 t = __hmin2(__hmax2(x, lo), hi);
    __nv_bfloat162 u = __hmul2(t, t);
    __nv_bfloat162 p = __hfma2(u, __float2bfloat162_rn(-2.10813e-4f),
                                  __float2bfloat162_rn(2.0833333e-3f));
    p = __hfma2(u, p, __float2bfloat162_rn(-2.0833333e-2f));
    p = __hfma2(u, p, __float2bfloat162_rn(2.5e-1f));
    __nv_bfloat162 s = __hfma2(t, p, __float2bfloat162_rn(0.5f));
    __nv_bfloat162 r = __hmul2(x, s);
    return *(uint32_t*)&r;
}
__device__ __forceinline__ unsigned long long umin64(unsigned long long a,
                                                     unsigned long long b){
    return a < b ? a : b;
}
__device__ __forceinline__ uint32_t smem_u32(const void* p){
    uint32_t a;
    asm("{ .reg .u64 t; cvta.to.shared.u64 t, %1; cvt.u32.u64 %0, t; }"
        : "=r"(a) : "l"(p));
    return a;
}
__device__ __forceinline__ void ldm_x4(uint32_t& r0, uint32_t& r1,
                                       uint32_t& r2, uint32_t& r3, uint32_t a){
    asm volatile("ldmatrix.sync.aligned.m8n8.x4.shared.b16 {%0,%1,%2,%3}, [%4];"
        : "=r"(r0), "=r"(r1), "=r"(r2), "=r"(r3) : "r"(a));
}
__device__ __forceinline__ void ldm_x2(uint32_t& r0, uint32_t& r1, uint32_t a){
    asm volatile("ldmatrix.sync.aligned.m8n8.x2.shared.b16 {%0,%1}, [%2];"
        : "=r"(r0), "=r"(r1) : "r"(a));
}

// ================ 0) prep: transposed/packed bf16 weights ================
__global__ void prep_kernel(const float* __restrict__ We1,
                            const float* __restrict__ be1,
                            const float* __restrict__ We2,
                            const float* __restrict__ Wc1)
{
    int t = blockIdx.x*256 + threadIdx.x;
    int stride = gridDim.x*256;
    // We2^T: coalesced reads (n inner)
    for (int i = t; i < 64*288; i += stride){
        int k2 = i >> 6, n = i & 63;
        int r0 = 2*k2;
        float v0 = (r0     < H1R) ? We2[(size_t)r0*MD + n]     : 0.f;
        float v1 = (r0 + 1 < H1R) ? We2[(size_t)(r0+1)*MD + n] : 0.f;
        __nv_bfloat162 p = __floats2bfloat162_rn(v0, v1);
        g_We2T[n*288 + k2] = *(uint32_t*)&p;
    }
    for (int i = t; i < 256*32; i += stride){
        int k2 = i >> 8, n = i & 255;
        float v0 = Wc1[(size_t)(2*k2)*256 + n];
        float v1 = Wc1[(size_t)(2*k2+1)*256 + n];
        __nv_bfloat162 p = __floats2bfloat162_rn(v0, v1);
        g_Wc1T[n*32 + k2] = *(uint32_t*)&p;
    }
    // We1^T halves: coalesced reads (n inner)
    for (int i = t; i < 64*576; i += stride){
        int w = i / 576, n = i % 576;
        float a0 = 0.f, a1 = 0.f, b0 = 0.f, b1 = 0.f;
        if (n < H1R){
            a0 = We1[(size_t)(2*w)*H1R + n];
            a1 = We1[(size_t)(2*w+1)*H1R + n];
            b0 = We1[(size_t)(128+2*w)*H1R + n];
            b1 = We1[(size_t)(128+2*w+1)*H1R + n];
        }
        __nv_bfloat162 pa = __floats2bfloat162_rn(a0, a1);
        __nv_bfloat162 pb = __floats2bfloat162_rn(b0, b1);
        g_We1Ta[n*64 + w] = *(uint32_t*)&pa;
        g_We1Tb[n*64 + w] = *(uint32_t*)&pb;
    }
    // packed fourier rows + bias
    for (int i = t; i < 9*288; i += stride){
        int s = i / 288, w = i % 288;
        int gc = 2*w;
        float v0 = (gc     < H1R) ? We1[(size_t)(256+s)*H1R + gc]     : 0.f;
        float v1 = (gc + 1 < H1R) ? We1[(size_t)(256+s)*H1R + gc + 1] : 0.f;
        __nv_bfloat162 p = __floats2bfloat162_rn(v0, v1);
        g_RWb[i] = *(uint32_t*)&p;
    }
    for (int i = t; i < 288; i += stride){
        int gc = 2*i;
        float v0 = (gc     < H1R) ? be1[gc]     : 0.f;
        float v1 = (gc + 1 < H1R) ? be1[gc + 1] : 0.f;
        __nv_bfloat162 p = __floats2bfloat162_rn(v0, v1);
        g_B1b[i] = *(uint32_t*)&p;
    }
}

// ======== 1) kNN top-32 per node (register-resident u64 keys) ============
__global__ void __launch_bounds__(256) topk_kernel(const float* __restrict__ coors)
{
    __shared__ unsigned long long red[8];
    __shared__ unsigned long long bcast;
    __shared__ int   selj[KNB];
    __shared__ float seld[KNB];

    int row = blockIdx.x;
    int b   = row / NPTS;
    int t   = threadIdx.x;
    const float* cb = coors + (size_t)b*NPTS*3;
    float cx = coors[(size_t)row*3+0];
    float cy = coors[(size_t)row*3+1];
    float cz = coors[(size_t)row*3+2];

    unsigned long long key[8];
    #pragma unroll
    for (int r = 0; r < 8; r++){
        int j = t + r*256;
        float dx = cx - cb[j*3+0];
        float dy = cy - cb[j*3+1];
        float dz = cz - cb[j*3+2];
        float d = dx*dx + dy*dy + dz*dz;
        key[r] = ((unsigned long long)__float_as_uint(d) << 32) | (unsigned)j;
    }

    for (int kk = 0; kk < KNB; kk++){
        unsigned long long best = key[0];
        #pragma unroll
        for (int r = 1; r < 8; r++) best = umin64(best, key[r]);
        #pragma unroll
        for (int o = 16; o > 0; o >>= 1){
            unsigned long long other = __shfl_down_sync(0xffffffffu, best, o);
            best = umin64(best, other);
        }
        if ((t & 31) == 0) red[t >> 5] = best;
        __syncthreads();
        if (t == 0){
            unsigned long long m = red[0];
            #pragma unroll
            for (int w = 1; w < 8; w++) m = umin64(m, red[w]);
            bcast = m;
            selj[kk] = (int)(m & 0xFFFFFFFFull);
            seld[kk] = __uint_as_float((unsigned)(m >> 32));
        }
        __syncthreads();
        int j = (int)(bcast & 0xFFFFFFFFull);
        if ((j & 255) == t) key[j >> 8] = 0xFFFFFFFFFFFFFFFFull;
    }

    if (t < KNB){
        int j = selj[t];
        size_t e = (size_t)row*KNB + t;
        g_idx [e] = j;
        g_reld[e] = seld[t];
        g_relc[e*3+0] = cx - cb[j*3+0];
        g_relc[e*3+1] = cy - cb[j*3+1];
        g_relc[e*3+2] = cz - cb[j*3+2];
    }
}

// ===== 2) P/Q via bf16 HMMA: [128 nodes] x [64 cols] x K=128 =============
__global__ void __launch_bounds__(256) pq_hmma(const float* __restrict__ feats)
{
    __shared__ uint32_t sA[128*36];
    __shared__ uint32_t sB[64*36];

    int which = blockIdx.z;
    uint32_t* C = which ? g_Qb : g_Pb;
    const uint32_t* WT = which ? g_We1Tb : g_We1Ta;
    int bn = blockIdx.x, bm = blockIdx.y;
    int t = threadIdx.x;
    int wid = t >> 5, lid = t & 31;
    int lr = lid >> 2, lc = lid & 3;
    int g8 = lid >> 3, l8 = lid & 7;

    uint32_t aBase = smem_u32(sA) +
        (((wid*16 + (g8 & 1)*8 + l8)*36 + (g8 >> 1)*4) << 2);
    uint32_t bBase = smem_u32(sB) + ((l8*36 + (g8 & 1)*4) << 2);

    float dacc[8][4];
    #pragma unroll
    for (int ni = 0; ni < 8; ni++)
        #pragma unroll
        for (int r = 0; r < 4; r++) dacc[ni][r] = 0.f;

    for (int ck = 0; ck < 2; ck++){
        #pragma unroll
        for (int it = 0; it < 8; it++){
            int lin = t + it*256;
            int rowi = lin >> 4;
            int f4  = lin & 15;
            float4 v = *(const float4*)(feats +
                (size_t)(bm*128 + rowi)*DD + ck*64 + f4*4);
            __nv_bfloat162 w0 = __floats2bfloat162_rn(v.x, v.y);
            __nv_bfloat162 w1 = __floats2bfloat162_rn(v.z, v.w);
            uint2 pk = make_uint2(*(uint32_t*)&w0, *(uint32_t*)&w1);
            *(uint2*)&sA[rowi*36 + f4*2] = pk;
        }
        #pragma unroll
        for (int h = 0; h < 2; h++){
            int lin = t + h*256;
            int n  = lin >> 3;
            int u4 = lin & 7;
            uint4 v = *(const uint4*)&WT[(size_t)(bn*64 + n)*64 + ck*32 + u4*4];
            *(uint4*)&sB[n*36 + u4*4] = v;
        }
        __syncthreads();

        #pragma unroll
        for (int ks = 0; ks < 4; ks++){
            uint32_t a0, a1, a2, a3;
            ldm_x4(a0, a1, a2, a3, aBase + ks*32);
            #pragma unroll
            for (int ni = 0; ni < 8; ni++){
                uint32_t b0, b1;
                ldm_x2(b0, b1, bBase + ni*1152 + ks*32);
                float* d = dacc[ni];
                asm volatile(
                    "mma.sync.aligned.m16n8k16.row.col.f32.bf16.bf16.f32 "
                    "{%0,%1,%2,%3}, {%4,%5,%6,%7}, {%8,%9}, {%0,%1,%2,%3};"
                    : "+f"(d[0]), "+f"(d[1]), "+f"(d[2]), "+f"(d[3])
                    : "r"(a0), "r"(a1), "r"(a2), "r"(a3),
                      "r"(b0), "r"(b1));
            }
        }
        __syncthreads();
    }

    int r0 = bm*128 + wid*16 + lr;
    #pragma unroll
    for (int ni = 0; ni < 8; ni++){
        float* d = dacc[ni];
        __nv_bfloat162 w0 = __floats2bfloat162_rn(d[0], d[1]);
        __nv_bfloat162 w1 = __floats2bfloat162_rn(d[2], d[3]);
        C[(size_t)r0*H1W     + bn*32 + ni*4 + lc] = *(uint32_t*)&w0;
        C[(size_t)(r0+8)*H1W + bn*32 + ni*4 + lc] = *(uint32_t*)&w1;
    }
}

// ==================== 3) fused edge pipeline (all-HMMA, ldmatrix) ========
#define U_SIZE 9472

__global__ void __launch_bounds__(256,3) edge_kernel(
    const float* __restrict__ coors,
    const float* __restrict__ be2,
    const float* __restrict__ bc1,
    const float* __restrict__ Wc2, const float* __restrict__ bc2,
    float* __restrict__ coors_out)
{
    __shared__ float smU[U_SIZE];
    __shared__ uint32_t sRD[128*10];   // bf16x2 broadcast fourier words
    __shared__ int   sIdx[128];
    __shared__ float sBe2[64];

    uint32_t* sA32 = (uint32_t*)smU;            // phase1 A / phase2 sMb
    uint32_t* sB32 = (uint32_t*)(smU + 4608);   // phase1 B / phase2 sWb
    uint32_t* sRWb = (uint32_t*)(smU + 6912);   // [9][32] packed fourier W
    uint32_t* sB1b = (uint32_t*)(smU + 7200);   // [32] packed bias
    uint32_t* sMb = sA32;
    uint32_t* sWb = sB32;
    float* sBc1 = smU + 9216;                   // [128]
    float* sWc2 = smU + 9344;                   // [128]
    float* sCw  = (float*)sRD;                  // alias after phase 1

    int t   = threadIdx.x;
    int wid = t >> 5;
    int lid = t & 31;
    int node0 = blockIdx.x * 4;
    int b = node0 / NPTS;
    int lr = lid >> 2, lc = lid & 3;
    int g8 = lid >> 3, l8 = lid & 7;

    uint32_t aBase = smem_u32(sA32) +
        (((wid*16 + (g8 & 1)*8 + l8)*36 + (g8 >> 1)*4) << 2);
    uint32_t bBase = smem_u32(sB32) + ((l8*36 + (g8 & 1)*4) << 2);

    // ---- prologue: fourier features, packed broadcast bf16x2 ----
    if (t < 128){
        int e = t;
        sIdx[e] = g_idx[(size_t)node0*KNB + e];
        float d = g_reld[(size_t)node0*KNB + e];
        float fr[9];
        fr[8] = d;
        float x = d;
        #pragma unroll
        for (int s = 0; s < 4; s++){
            fr[s]     = sinf(x);
            fr[4 + s] = cosf(x);
            x *= 0.5f;
        }
        uint32_t* rb = &sRD[e*10];
        #pragma unroll
        for (int s = 0; s < 9; s++){
            uint16_t us = __bfloat16_as_ushort(__float2bfloat16(fr[s]));
            rb[s] = (uint32_t)us | ((uint32_t)us << 16);
        }
    }
    if (t < 64) sBe2[t] = be2[t];

    float dacc[8][4];
    #pragma unroll
    for (int ni = 0; ni < 8; ni++)
        #pragma unroll
        for (int r = 0; r < 4; r++) dacc[ni][r] = 0.f;

    for (int chunk = 0; chunk < 9; chunk++){
        int c0w = chunk*32;

        for (int lin = t; lin < 288; lin += 256){
            int s = lin >> 5, w = lin & 31;
            sRWb[s*32 + w] = g_RWb[s*288 + c0w + w];
        }
        if (t < 32) sB1b[t] = g_B1b[c0w + t];
        #pragma unroll
        for (int h = 0; h < 2; h++){
            int lin = t + h*256;
            int n  = lin >> 3;
            int u4 = lin & 7;
            uint4 v = *(const uint4*)&g_We2T[n*288 + c0w + u4*4];
            *(uint4*)&sB32[n*36 + u4*4] = v;
        }
        __syncthreads();

        // h1 assembly (bf16x2, uint4-wide): 4 its x 4 words
        #pragma unroll
        for (int it = 0; it < 4; it++){
            int lin = t + it*256;         // 0..1023
            int e  = lin >> 3;            // 0..127
            int w4 = (lin & 7) * 4;       // 0,4,..,28
            int gi = node0 + (e >> 5);
            uint4 pw = *(const uint4*)&g_Pb[(size_t)gi*H1W + c0w + w4];
            uint4 qw = *(const uint4*)&g_Qb[(size_t)(b*NPTS + sIdx[e])*H1W + c0w + w4];
            uint4 bw = *(const uint4*)&sB1b[w4];
            __nv_bfloat162 h0 = __hadd2(__hadd2(*(__nv_bfloat162*)&pw.x,
                                                *(__nv_bfloat162*)&qw.x),
                                        *(__nv_bfloat162*)&bw.x);
            __nv_bfloat162 h1 = __hadd2(__hadd2(*(__nv_bfloat162*)&pw.y,
                                                *(__nv_bfloat162*)&qw.y),
                                        *(__nv_bfloat162*)&bw.y);
            __nv_bfloat162 h2 = __hadd2(__hadd2(*(__nv_bfloat162*)&pw.z,
                                                *(__nv_bfloat162*)&qw.z),
                                        *(__nv_bfloat162*)&bw.z);
            __nv_bfloat162 h3 = __hadd2(__hadd2(*(__nv_bfloat162*)&pw.w,
                                                *(__nv_bfloat162*)&qw.w),
                                        *(__nv_bfloat162*)&bw.w);
            const uint32_t* rb = &sRD[e*10];
            #pragma unroll
            for (int s = 0; s < 9; s++){
                uint32_t rvw = rb[s];
                __nv_bfloat162 rv = *(__nv_bfloat162*)&rvw;
                uint4 ww = *(const uint4*)&sRWb[s*32 + w4];
                h0 = __hfma2(rv, *(__nv_bfloat162*)&ww.x, h0);
                h1 = __hfma2(rv, *(__nv_bfloat162*)&ww.y, h1);
                h2 = __hfma2(rv, *(__nv_bfloat162*)&ww.z, h2);
                h3 = __hfma2(rv, *(__nv_bfloat162*)&ww.w, h3);
            }
            uint4 outw = make_uint4(silu2(h0), silu2(h1), silu2(h2), silu2(h3));
            *(uint4*)&sA32[e*36 + w4] = outw;
        }
        __syncthreads();

        // HMMA with ldmatrix fragments
        #pragma unroll
        for (int ks = 0; ks < 4; ks++){
            uint32_t a0, a1, a2, a3;
            ldm_x4(a0, a1, a2, a3, aBase + ks*32);
            #pragma unroll
            for (int ni = 0; ni < 8; ni++){
                uint32_t b0, b1;
                ldm_x2(b0, b1, bBase + ni*1152 + ks*32);
                float* d = dacc[ni];
                asm volatile(
                    "mma.sync.aligned.m16n8k16.row.col.f32.bf16.bf16.f32 "
                    "{%0,%1,%2,%3}, {%4,%5,%6,%7}, {%8,%9}, {%0,%1,%2,%3};"
                    : "+f"(d[0]), "+f"(d[1]), "+f"(d[2]), "+f"(d[3])
                    : "r"(a0), "r"(a1), "r"(a2), "r"(a3),
                      "r"(b0), "r"(b1));
            }
        }
        __syncthreads();
    }

    // ---- epilogue: m = silu(D + be2) -> bf16 sMb [128][36] words ----
    {
        int r0 = wid*16 + lr;
        #pragma unroll
        for (int ni = 0; ni < 8; ni++){
            int c = ni*8 + lc*2;
            float b0v = sBe2[c], b1v = sBe2[c+1];
            float* d = dacc[ni];
            __nv_bfloat162 m0 = __floats2bfloat162_rn(silu_p(d[0]+b0v), silu_p(d[1]+b1v));
            __nv_bfloat162 m1 = __floats2bfloat162_rn(silu_p(d[2]+b0v), silu_p(d[3]+b1v));
            sMb[r0*36 + ni*4 + lc]     = *(uint32_t*)&m0;
            sMb[(r0+8)*36 + ni*4 + lc] = *(uint32_t*)&m1;
        }
    }
    __syncthreads();

    // ---- m_i: sum m over K=32 neighbors (from bf16 m) ----
    if (t < 128){
        int ni2 = t >> 5;
        int wq  = t & 31;
        float s0 = 0.f, s1 = 0.f;
        #pragma unroll 8
        for (int kk = 0; kk < 32; kk++){
            uint32_t w = sMb[(ni2*32 + kk)*36 + wq];
            __nv_bfloat162 h2 = *(__nv_bfloat162*)&w;
            s0 += __bfloat162float(__low2bfloat16(h2));
            s1 += __bfloat162float(__high2bfloat16(h2));
        }
        g_mi[(size_t)(node0 + ni2)*MD + 2*wq]     = s0;
        g_mi[(size_t)(node0 + ni2)*MD + 2*wq + 1] = s1;
    }

    // ---- coors MLP layer1 via HMMA (ldmatrix), folded through silu*Wc2 --
    uint32_t af[4][4];
    #pragma unroll
    for (int ks = 0; ks < 4; ks++)
        ldm_x4(af[ks][0], af[ks][1], af[ks][2], af[ks][3], aBase + ks*32);

    float cw0 = 0.f, cw1 = 0.f;
    for (int hf = 0; hf < 2; hf++){
        __syncthreads();
        #pragma unroll
        for (int h = 0; h < 4; h++){
            int lin = t + h*256;
            int n  = lin >> 3;
            int u4 = lin & 7;
            uint4 v = *(const uint4*)&g_Wc1T[(hf*128 + n)*32 + u4*4];
            *(uint4*)&sWb[n*36 + u4*4] = v;
        }
        if (t < 128) sBc1[t] = bc1[hf*128 + t];
        else         sWc2[t-128] = Wc2[hf*128 + (t-128)];
        __syncthreads();
        #pragma unroll
        for (int ni = 0; ni < 16; ni++){
            float d0 = 0.f, d1 = 0.f, d2 = 0.f, d3 = 0.f;
            #pragma unroll
            for (int ks = 0; ks < 4; ks++){
                uint32_t b0, b1;
                ldm_x2(b0, b1, bBase + ni*1152 + ks*32);
                asm volatile(
                    "mma.sync.aligned.m16n8k16.row.col.f32.bf16.bf16.f32 "
                    "{%0,%1,%2,%3}, {%4,%5,%6,%7}, {%8,%9}, {%0,%1,%2,%3};"
                    : "+f"(d0), "+f"(d1), "+f"(d2), "+f"(d3)
                    : "r"(af[ks][0]), "r"(af[ks][1]),
                      "r"(af[ks][2]), "r"(af[ks][3]),
                      "r"(b0), "r"(b1));
            }
            int cl = ni*8 + lc*2;
            float bb0 = sBc1[cl], bb1 = sBc1[cl+1];
            float w0 = sWc2[cl],  w1 = sWc2[cl+1];
            cw0 += silu_p(d0 + bb0)*w0 + silu_p(d1 + bb1)*w1;
            cw1 += silu_p(d2 + bb0)*w0 + silu_p(d3 + bb1)*w1;
        }
    }
    cw0 += __shfl_xor_sync(0xffffffffu, cw0, 1);
    cw0 += __shfl_xor_sync(0xffffffffu, cw0, 2);
    cw1 += __shfl_xor_sync(0xffffffffu, cw1, 1);
    cw1 += __shfl_xor_sync(0xffffffffu, cw1, 2);
    __syncthreads();
    if (lc == 0){
        sCw[wid*16 + lr]     = cw0;
        sCw[wid*16 + lr + 8] = cw1;
    }
    __syncthreads();

    // ---- coordinate update (residual) ----
    if (t < 12){
        int ni = t / 3, dim = t % 3;
        float bc2v = bc2[0];
        float ds = 0.f;
        for (int kk = 0; kk < 32; kk++){
            int e = ni*32 + kk;
            float cwv = sCw[e] + bc2v;
            ds += cwv * g_relc[((size_t)(node0 + ni)*KNB + kk)*3 + dim];
        }
        coors_out[(size_t)(node0 + ni)*3 + dim] =
            coors[(size_t)(node0 + ni)*3 + dim] + ds;
    }
}

// ==================== 4) node MLP (+ residual) ===========================
__global__ void __launch_bounds__(256) node_kernel(
    const float* __restrict__ feats,
    const float* __restrict__ Wn1, const float* __restrict__ bn1,
    const float* __restrict__ Wn2, const float* __restrict__ bn2,
    float* __restrict__ out)
{
    __shared__ float nin[8][192];
    __shared__ float hh [8][256];
    int n0 = blockIdx.x * 8;
    int t  = threadIdx.x;

    #pragma unroll
    for (int h = 0; h < 6; h++){
        int lin = t + h*256;
        int u = lin / 192, c = lin % 192;
        float v = (c < DD) ? feats[(size_t)(n0 + u)*DD + c]
                           : g_mi [(size_t)(n0 + u)*MD + (c - DD)];
        nin[u][c] = v;
    }
    __syncthreads();

    float a[8];
    #pragma unroll
    for (int u = 0; u < 8; u++) a[u] = bn1[t];
    for (int k = 0; k < 192; k++){
        float w = Wn1[(size_t)k*256 + t];
        #pragma unroll
        for (int u = 0; u < 8; u++) a[u] += nin[u][k]*w;
    }
    #pragma unroll
    for (int u = 0; u < 8; u++) hh[u][t] = silu_p(a[u]);
    __syncthreads();

    int col = t & 127, ug = t >> 7;
    float acc2[4];
    #pragma unroll
    for (int h = 0; h < 4; h++) acc2[h] = bn2[col];
    for (int k = 0; k < 256; k++){
        float w = Wn2[(size_t)k*DD + col];
        #pragma unroll
        for (int h = 0; h < 4; h++)
            acc2[h] += hh[ug + 2*h][k] * w;
    }
    #pragma unroll
    for (int h = 0; h < 4; h++){
        int u = ug + 2*h;
        out[(size_t)(n0 + u)*DD + col] =
            acc2[h] + feats[(size_t)(n0 + u)*DD + col];
    }
}

// ============================ launch =====================================
extern "C" void kernel_launch(void* const* d_in, const int* in_sizes, int n_in,
                              void* d_out, int out_size)
{
    (void)in_sizes; (void)n_in; (void)out_size;
    const float* feats = (const float*)d_in[0];
    const float* coors = (const float*)d_in[1];
    const float* We1   = (const float*)d_in[2];
    const float* be1   = (const float*)d_in[3];
    const float* We2   = (const float*)d_in[4];
    const float* be2   = (const float*)d_in[5];
    const float* Wc1   = (const float*)d_in[6];
    const float* bc1   = (const float*)d_in[7];
    const float* Wc2   = (const float*)d_in[8];
    const float* bc2   = (const float*)d_in[9];
    const float* Wn1   = (const float*)d_in[10];
    const float* bn1   = (const float*)d_in[11];
    const float* Wn2   = (const float*)d_in[12];
    const float* bn2   = (const float*)d_in[13];

    float* node_out  = (float*)d_out;
    float* coors_out = node_out + (size_t)NNODES*DD;

    prep_kernel<<<64, 256>>>(We1, be1, We2, Wc1);
    topk_kernel<<<NNODES, 256>>>(coors);
    pq_hmma<<<dim3(9, 64, 2), 256>>>(feats);
    edge_kernel<<<NNODES/4, 256>>>(coors, be2, bc1, Wc2, bc2, coors_out);
    node_kernel<<<NNODES/8, 256>>>(feats, Wn1, bn1, Wn2, bn2, node_out);
}

// round 16
// speedup vs baseline: 1.0321x; 1.0321x over previous
#include <cuda_runtime.h>
#include <cuda_bf16.h>
#include <math.h>
#include <stdint.h>

#define BB    4
#define NPTS  2048
#define DD    128
#define KNB   32
#define MD    64
#define H1P   576
#define H1W   288
#define H1R   530
#define NNODES (BB*NPTS)
#define NEDGES (NNODES*KNB)

// ---------------- device scratch ----------------
__device__ int   g_idx [NEDGES];
__device__ float g_relc[NEDGES*3];
__device__ float g_reld[NEDGES];
__device__ uint32_t g_Pb[(size_t)NNODES*H1W];
__device__ uint32_t g_Qb[(size_t)NNODES*H1W];
__device__ float g_mi  [(size_t)NNODES*MD];
__device__ uint32_t g_We2T[64*288];
__device__ uint32_t g_Wc1T[256*32];
__device__ uint32_t g_We1Ta[576*64];
__device__ uint32_t g_We1Tb[576*64];
__device__ uint32_t g_RWb[9*288];
__device__ uint32_t g_B1b[288];

__device__ __forceinline__ float silu_p(float x){
    float t = fminf(fmaxf(x, -2.f), 2.f);
    float u = t*t;
    float p = fmaf(u, -2.10813e-4f, 2.0833333e-3f);
    p = fmaf(u, p, -2.0833333e-2f);
    p = fmaf(u, p, 2.5e-1f);
    return x * fmaf(t, p, 0.5f);
}
__device__ __forceinline__ uint32_t silu2(__nv_bfloat162 x){
    __nv_bfloat162 hi = __float2bfloat162_rn(2.f);
    __nv_bfloat162 lo = __float2bfloat162_rn(-2.f);
    __nv_bfloat162 t = __hmin2(__hmax2(x, lo), hi);
    __nv_bfloat162 u = __hmul2(t, t);
    __nv_bfloat162 p = __hfma2(u, __float2bfloat162_rn(-2.10813e-4f),
                                  __float2bfloat162_rn(2.0833333e-3f));
    p = __hfma2(u, p, __float2bfloat162_rn(-2.0833333e-2f));
    p = __hfma2(u, p, __float2bfloat162_rn(2.5e-1f));
    __nv_bfloat162 s = __hfma2(t, p, __float2bfloat162_rn(0.5f));
    __nv_bfloat162 r = __hmul2(x, s);
    return *(uint32_t*)&r;
}
__device__ __forceinline__ unsigned long long umin64(unsigned long long a,
                                                     unsigned long long b){
    return a < b ? a : b;
}
__device__ __forceinline__ uint32_t smem_u32(const void* p){
    uint32_t a;
    asm("{ .reg .u64 t; cvta.to.shared.u64 t, %1; cvt.u32.u64 %0, t; }"
        : "=r"(a) : "l"(p));
    return a;
}
__device__ __forceinline__ void ldm_x4(uint32_t& r0, uint32_t& r1,
                                       uint32_t& r2, uint32_t& r3, uint32_t a){
    asm volatile("ldmatrix.sync.aligned.m8n8.x4.shared.b16 {%0,%1,%2,%3}, [%4];"
        : "=r"(r0), "=r"(r1), "=r"(r2), "=r"(r3) : "r"(a));
}
__device__ __forceinline__ void ldm_x2(uint32_t& r0, uint32_t& r1, uint32_t a){
    asm volatile("ldmatrix.sync.aligned.m8n8.x2.shared.b16 {%0,%1}, [%2];"
        : "=r"(r0), "=r"(r1) : "r"(a));
}

// ================ 0) prep: transposed/packed bf16 weights ================
__global__ void prep_kernel(const float* __restrict__ We1,
                            const float* __restrict__ be1,
                            const float* __restrict__ We2,
                            const float* __restrict__ Wc1)
{
    int t = blockIdx.x*256 + threadIdx.x;
    int stride = gridDim.x*256;
    for (int i = t; i < 64*288; i += stride){
        int k2 = i >> 6, n = i & 63;
        int r0 = 2*k2;
        float v0 = (r0     < H1R) ? We2[(size_t)r0*MD + n]     : 0.f;
        float v1 = (r0 + 1 < H1R) ? We2[(size_t)(r0+1)*MD + n] : 0.f;
        __nv_bfloat162 p = __floats2bfloat162_rn(v0, v1);
        g_We2T[n*288 + k2] = *(uint32_t*)&p;
    }
    for (int i = t; i < 256*32; i += stride){
        int k2 = i >> 8, n = i & 255;
        float v0 = Wc1[(size_t)(2*k2)*256 + n];
        float v1 = Wc1[(size_t)(2*k2+1)*256 + n];
        __nv_bfloat162 p = __floats2bfloat162_rn(v0, v1);
        g_Wc1T[n*32 + k2] = *(uint32_t*)&p;
    }
    for (int i = t; i < 64*576; i += stride){
        int w = i / 576, n = i % 576;
        float a0 = 0.f, a1 = 0.f, b0 = 0.f, b1 = 0.f;
        if (n < H1R){
            a0 = We1[(size_t)(2*w)*H1R + n];
            a1 = We1[(size_t)(2*w+1)*H1R + n];
            b0 = We1[(size_t)(128+2*w)*H1R + n];
            b1 = We1[(size_t)(128+2*w+1)*H1R + n];
        }
        __nv_bfloat162 pa = __floats2bfloat162_rn(a0, a1);
        __nv_bfloat162 pb = __floats2bfloat162_rn(b0, b1);
        g_We1Ta[n*64 + w] = *(uint32_t*)&pa;
        g_We1Tb[n*64 + w] = *(uint32_t*)&pb;
    }
    for (int i = t; i < 9*288; i += stride){
        int s = i / 288, w = i % 288;
        int gc = 2*w;
        float v0 = (gc     < H1R) ? We1[(size_t)(256+s)*H1R + gc]     : 0.f;
        float v1 = (gc + 1 < H1R) ? We1[(size_t)(256+s)*H1R + gc + 1] : 0.f;
        __nv_bfloat162 p = __floats2bfloat162_rn(v0, v1);
        g_RWb[i] = *(uint32_t*)&p;
    }
    for (int i = t; i < 288; i += stride){
        int gc = 2*i;
        float v0 = (gc     < H1R) ? be1[gc]     : 0.f;
        float v1 = (gc + 1 < H1R) ? be1[gc + 1] : 0.f;
        __nv_bfloat162 p = __floats2bfloat162_rn(v0, v1);
        g_B1b[i] = *(uint32_t*)&p;
    }
}

// ======== 1) kNN top-32 per node (round-12 smem version, known-good) =====
__global__ void __launch_bounds__(256) topk_kernel(const float* __restrict__ coors)
{
    __shared__ float dist[NPTS];
    __shared__ unsigned long long red[8];
    __shared__ int   selj[KNB];
    __shared__ float seld[KNB];

    int row = blockIdx.x;
    int b   = row / NPTS;
    int t   = threadIdx.x;
    const float* cb = coors + (size_t)b*NPTS*3;
    float cx = coors[(size_t)row*3+0];
    float cy = coors[(size_t)row*3+1];
    float cz = coors[(size_t)row*3+2];

    for (int j = t; j < NPTS; j += 256){
        float dx = cx - cb[j*3+0];
        float dy = cy - cb[j*3+1];
        float dz = cz - cb[j*3+2];
        dist[j] = dx*dx + dy*dy + dz*dz;
    }
    __syncthreads();

    for (int kk = 0; kk < KNB; kk++){
        unsigned long long best = 0xFFFFFFFFFFFFFFFFull;
        #pragma unroll
        for (int r = 0; r < NPTS/256; r++){
            int j = t + r*256;
            unsigned int fb = __float_as_uint(dist[j]);
            unsigned long long key = ((unsigned long long)fb << 32) | (unsigned)j;
            best = umin64(best, key);
        }
        #pragma unroll
        for (int o = 16; o > 0; o >>= 1){
            unsigned long long other = __shfl_down_sync(0xffffffffu, best, o);
            best = umin64(best, other);
        }
        if ((t & 31) == 0) red[t >> 5] = best;
        __syncthreads();
        if (t == 0){
            unsigned long long m = red[0];
            #pragma unroll
            for (int w = 1; w < 8; w++) m = umin64(m, red[w]);
            int j = (int)(m & 0xFFFFFFFFull);
            selj[kk] = j;
            seld[kk] = __uint_as_float((unsigned)(m >> 32));
            dist[j]  = __uint_as_float(0x7F800000u);
        }
        __syncthreads();
    }

    if (t < KNB){
        int j = selj[t];
        size_t e = (size_t)row*KNB + t;
        g_idx [e] = j;
        g_reld[e] = seld[t];
        g_relc[e*3+0] = cx - cb[j*3+0];
        g_relc[e*3+1] = cy - cb[j*3+1];
        g_relc[e*3+2] = cz - cb[j*3+2];
    }
}

// ===== 2) P/Q via bf16 HMMA =============================================
__global__ void __launch_bounds__(256) pq_hmma(const float* __restrict__ feats)
{
    __shared__ uint32_t sA[128*36];
    __shared__ uint32_t sB[64*36];

    int which = blockIdx.z;
    uint32_t* C = which ? g_Qb : g_Pb;
    const uint32_t* WT = which ? g_We1Tb : g_We1Ta;
    int bn = blockIdx.x, bm = blockIdx.y;
    int t = threadIdx.x;
    int wid = t >> 5, lid = t & 31;
    int lr = lid >> 2, lc = lid & 3;
    int g8 = lid >> 3, l8 = lid & 7;

    uint32_t aBase = smem_u32(sA) +
        (((wid*16 + (g8 & 1)*8 + l8)*36 + (g8 >> 1)*4) << 2);
    uint32_t bBase = smem_u32(sB) + ((l8*36 + (g8 & 1)*4) << 2);

    float dacc[8][4];
    #pragma unroll
    for (int ni = 0; ni < 8; ni++)
        #pragma unroll
        for (int r = 0; r < 4; r++) dacc[ni][r] = 0.f;

    for (int ck = 0; ck < 2; ck++){
        #pragma unroll
        for (int it = 0; it < 8; it++){
            int lin = t + it*256;
            int rowi = lin >> 4;
            int f4  = lin & 15;
            float4 v = *(const float4*)(feats +
                (size_t)(bm*128 + rowi)*DD + ck*64 + f4*4);
            __nv_bfloat162 w0 = __floats2bfloat162_rn(v.x, v.y);
            __nv_bfloat162 w1 = __floats2bfloat162_rn(v.z, v.w);
            uint2 pk = make_uint2(*(uint32_t*)&w0, *(uint32_t*)&w1);
            *(uint2*)&sA[rowi*36 + f4*2] = pk;
        }
        #pragma unroll
        for (int h = 0; h < 2; h++){
            int lin = t + h*256;
            int n  = lin >> 3;
            int u4 = lin & 7;
            uint4 v = *(const uint4*)&WT[(size_t)(bn*64 + n)*64 + ck*32 + u4*4];
            *(uint4*)&sB[n*36 + u4*4] = v;
        }
        __syncthreads();

        #pragma unroll
        for (int ks = 0; ks < 4; ks++){
            uint32_t a0, a1, a2, a3;
            ldm_x4(a0, a1, a2, a3, aBase + ks*32);
            #pragma unroll
            for (int ni = 0; ni < 8; ni++){
                uint32_t b0, b1;
                ldm_x2(b0, b1, bBase + ni*1152 + ks*32);
                float* d = dacc[ni];
                asm volatile(
                    "mma.sync.aligned.m16n8k16.row.col.f32.bf16.bf16.f32 "
                    "{%0,%1,%2,%3}, {%4,%5,%6,%7}, {%8,%9}, {%0,%1,%2,%3};"
                    : "+f"(d[0]), "+f"(d[1]), "+f"(d[2]), "+f"(d[3])
                    : "r"(a0), "r"(a1), "r"(a2), "r"(a3),
                      "r"(b0), "r"(b1));
            }
        }
        __syncthreads();
    }

    int r0 = bm*128 + wid*16 + lr;
    #pragma unroll
    for (int ni = 0; ni < 8; ni++){
        float* d = dacc[ni];
        __nv_bfloat162 w0 = __floats2bfloat162_rn(d[0], d[1]);
        __nv_bfloat162 w1 = __floats2bfloat162_rn(d[2], d[3]);
        C[(size_t)r0*H1W     + bn*32 + ni*4 + lc] = *(uint32_t*)&w0;
        C[(size_t)(r0+8)*H1W + bn*32 + ni*4 + lc] = *(uint32_t*)&w1;
    }
}

// ==================== 3) fused edge pipeline (all-HMMA, ldmatrix) ========
#define U_SIZE 9472

__global__ void __launch_bounds__(256,3) edge_kernel(
    const float* __restrict__ coors,
    const float* __restrict__ be2,
    const float* __restrict__ bc1,
    const float* __restrict__ Wc2, const float* __restrict__ bc2,
    float* __restrict__ coors_out)
{
    __shared__ float smU[U_SIZE];
    __shared__ uint32_t sRD[128*10];
    __shared__ int   sIdx[128];
    __shared__ float sBe2[64];

    uint32_t* sA32 = (uint32_t*)smU;
    uint32_t* sB32 = (uint32_t*)(smU + 4608);
    uint32_t* sRWb = (uint32_t*)(smU + 6912);
    uint32_t* sB1b = (uint32_t*)(smU + 7200);
    uint32_t* sMb = sA32;
    uint32_t* sWb = sB32;
    float* sBc1 = smU + 9216;
    float* sWc2 = smU + 9344;
    float* sCw  = (float*)sRD;

    int t   = threadIdx.x;
    int wid = t >> 5;
    int lid = t & 31;
    int node0 = blockIdx.x * 4;
    int b = node0 / NPTS;
    int lr = lid >> 2, lc = lid & 3;
    int g8 = lid >> 3, l8 = lid & 7;

    uint32_t aBase = smem_u32(sA32) +
        (((wid*16 + (g8 & 1)*8 + l8)*36 + (g8 >> 1)*4) << 2);
    uint32_t bBase = smem_u32(sB32) + ((l8*36 + (g8 & 1)*4) << 2);

    if (t < 128){
        int e = t;
        sIdx[e] = g_idx[(size_t)node0*KNB + e];
        float d = g_reld[(size_t)node0*KNB + e];
        float fr[9];
        fr[8] = d;
        float x = d;
        #pragma unroll
        for (int s = 0; s < 4; s++){
            fr[s]     = sinf(x);
            fr[4 + s] = cosf(x);
            x *= 0.5f;
        }
        uint32_t* rb = &sRD[e*10];
        #pragma unroll
        for (int s = 0; s < 9; s++){
            uint16_t us = __bfloat16_as_ushort(__float2bfloat16(fr[s]));
            rb[s] = (uint32_t)us | ((uint32_t)us << 16);
        }
    }
    if (t < 64) sBe2[t] = be2[t];

    float dacc[8][4];
    #pragma unroll
    for (int ni = 0; ni < 8; ni++)
        #pragma unroll
        for (int r = 0; r < 4; r++) dacc[ni][r] = 0.f;

    for (int chunk = 0; chunk < 9; chunk++){
        int c0w = chunk*32;

        for (int lin = t; lin < 288; lin += 256){
            int s = lin >> 5, w = lin & 31;
            sRWb[s*32 + w] = g_RWb[s*288 + c0w + w];
        }
        if (t < 32) sB1b[t] = g_B1b[c0w + t];
        #pragma unroll
        for (int h = 0; h < 2; h++){
            int lin = t + h*256;
            int n  = lin >> 3;
            int u4 = lin & 7;
            uint4 v = *(const uint4*)&g_We2T[n*288 + c0w + u4*4];
            *(uint4*)&sB32[n*36 + u4*4] = v;
        }
        __syncthreads();

        #pragma unroll
        for (int it = 0; it < 4; it++){
            int lin = t + it*256;
            int e  = lin >> 3;
            int w4 = (lin & 7) * 4;
            int gi = node0 + (e >> 5);
            uint4 pw = *(const uint4*)&g_Pb[(size_t)gi*H1W + c0w + w4];
            uint4 qw = *(const uint4*)&g_Qb[(size_t)(b*NPTS + sIdx[e])*H1W + c0w + w4];
            uint4 bw = *(const uint4*)&sB1b[w4];
            __nv_bfloat162 h0 = __hadd2(__hadd2(*(__nv_bfloat162*)&pw.x,
                                                *(__nv_bfloat162*)&qw.x),
                                        *(__nv_bfloat162*)&bw.x);
            __nv_bfloat162 h1 = __hadd2(__hadd2(*(__nv_bfloat162*)&pw.y,
                                                *(__nv_bfloat162*)&qw.y),
                                        *(__nv_bfloat162*)&bw.y);
            __nv_bfloat162 h2 = __hadd2(__hadd2(*(__nv_bfloat162*)&pw.z,
                                                *(__nv_bfloat162*)&qw.z),
                                        *(__nv_bfloat162*)&bw.z);
            __nv_bfloat162 h3 = __hadd2(__hadd2(*(__nv_bfloat162*)&pw.w,
                                                *(__nv_bfloat162*)&qw.w),
                                        *(__nv_bfloat162*)&bw.w);
            const uint32_t* rb = &sRD[e*10];
            #pragma unroll
            for (int s = 0; s < 9; s++){
                uint32_t rvw = rb[s];
                __nv_bfloat162 rv = *(__nv_bfloat162*)&rvw;
                uint4 ww = *(const uint4*)&sRWb[s*32 + w4];
                h0 = __hfma2(rv, *(__nv_bfloat162*)&ww.x, h0);
                h1 = __hfma2(rv, *(__nv_bfloat162*)&ww.y, h1);
                h2 = __hfma2(rv, *(__nv_bfloat162*)&ww.z, h2);
                h3 = __hfma2(rv, *(__nv_bfloat162*)&ww.w, h3);
            }
            uint4 outw = make_uint4(silu2(h0), silu2(h1), silu2(h2), silu2(h3));
            *(uint4*)&sA32[e*36 + w4] = outw;
        }
        __syncthreads();

        #pragma unroll
        for (int ks = 0; ks < 4; ks++){
            uint32_t a0, a1, a2, a3;
            ldm_x4(a0, a1, a2, a3, aBase + ks*32);
            #pragma unroll
            for (int ni = 0; ni < 8; ni++){
                uint32_t b0, b1;
                ldm_x2(b0, b1, bBase + ni*1152 + ks*32);
                float* d = dacc[ni];
                asm volatile(
                    "mma.sync.aligned.m16n8k16.row.col.f32.bf16.bf16.f32 "
                    "{%0,%1,%2,%3}, {%4,%5,%6,%7}, {%8,%9}, {%0,%1,%2,%3};"
                    : "+f"(d[0]), "+f"(d[1]), "+f"(d[2]), "+f"(d[3])
                    : "r"(a0), "r"(a1), "r"(a2), "r"(a3),
                      "r"(b0), "r"(b1));
            }
        }
        __syncthreads();
    }

    {
        int r0 = wid*16 + lr;
        #pragma unroll
        for (int ni = 0; ni < 8; ni++){
            int c = ni*8 + lc*2;
            float b0v = sBe2[c], b1v = sBe2[c+1];
            float* d = dacc[ni];
            __nv_bfloat162 m0 = __floats2bfloat162_rn(silu_p(d[0]+b0v), silu_p(d[1]+b1v));
            __nv_bfloat162 m1 = __floats2bfloat162_rn(silu_p(d[2]+b0v), silu_p(d[3]+b1v));
            sMb[r0*36 + ni*4 + lc]     = *(uint32_t*)&m0;
            sMb[(r0+8)*36 + ni*4 + lc] = *(uint32_t*)&m1;
        }
    }
    __syncthreads();

    if (t < 128){
        int ni2 = t >> 5;
        int wq  = t & 31;
        float s0 = 0.f, s1 = 0.f;
        #pragma unroll 8
        for (int kk = 0; kk < 32; kk++){
            uint32_t w = sMb[(ni2*32 + kk)*36 + wq];
            __nv_bfloat162 h2 = *(__nv_bfloat162*)&w;
            s0 += __bfloat162float(__low2bfloat16(h2));
            s1 += __bfloat162float(__high2bfloat16(h2));
        }
        g_mi[(size_t)(node0 + ni2)*MD + 2*wq]     = s0;
        g_mi[(size_t)(node0 + ni2)*MD + 2*wq + 1] = s1;
    }

    uint32_t af[4][4];
    #pragma unroll
    for (int ks = 0; ks < 4; ks++)
        ldm_x4(af[ks][0], af[ks][1], af[ks][2], af[ks][3], aBase + ks*32);

    float cw0 = 0.f, cw1 = 0.f;
    for (int hf = 0; hf < 2; hf++){
        __syncthreads();
        #pragma unroll
        for (int h = 0; h < 4; h++){
            int lin = t + h*256;
            int n  = lin >> 3;
            int u4 = lin & 7;
            uint4 v = *(const uint4*)&g_Wc1T[(hf*128 + n)*32 + u4*4];
            *(uint4*)&sWb[n*36 + u4*4] = v;
        }
        if (t < 128) sBc1[t] = bc1[hf*128 + t];
        else         sWc2[t-128] = Wc2[hf*128 + (t-128)];
        __syncthreads();
        #pragma unroll
        for (int ni = 0; ni < 16; ni++){
            float d0 = 0.f, d1 = 0.f, d2 = 0.f, d3 = 0.f;
            #pragma unroll
            for (int ks = 0; ks < 4; ks++){
                uint32_t b0, b1;
                ldm_x2(b0, b1, bBase + ni*1152 + ks*32);
                asm volatile(
                    "mma.sync.aligned.m16n8k16.row.col.f32.bf16.bf16.f32 "
                    "{%0,%1,%2,%3}, {%4,%5,%6,%7}, {%8,%9}, {%0,%1,%2,%3};"
                    : "+f"(d0), "+f"(d1), "+f"(d2), "+f"(d3)
                    : "r"(af[ks][0]), "r"(af[ks][1]),
                      "r"(af[ks][2]), "r"(af[ks][3]),
                      "r"(b0), "r"(b1));
            }
            int cl = ni*8 + lc*2;
            float bb0 = sBc1[cl], bb1 = sBc1[cl+1];
            float w0 = sWc2[cl],  w1 = sWc2[cl+1];
            cw0 += silu_p(d0 + bb0)*w0 + silu_p(d1 + bb1)*w1;
            cw1 += silu_p(d2 + bb0)*w0 + silu_p(d3 + bb1)*w1;
        }
    }
    cw0 += __shfl_xor_sync(0xffffffffu, cw0, 1);
    cw0 += __shfl_xor_sync(0xffffffffu, cw0, 2);
    cw1 += __shfl_xor_sync(0xffffffffu, cw1, 1);
    cw1 += __shfl_xor_sync(0xffffffffu, cw1, 2);
    __syncthreads();
    if (lc == 0){
        sCw[wid*16 + lr]     = cw0;
        sCw[wid*16 + lr + 8] = cw1;
    }
    __syncthreads();

    if (t < 12){
        int ni = t / 3, dim = t % 3;
        float bc2v = bc2[0];
        float ds = 0.f;
        for (int kk = 0; kk < 32; kk++){
            int e = ni*32 + kk;
            float cwv = sCw[e] + bc2v;
            ds += cwv * g_relc[((size_t)(node0 + ni)*KNB + kk)*3 + dim];
        }
        coors_out[(size_t)(node0 + ni)*3 + dim] =
            coors[(size_t)(node0 + ni)*3 + dim] + ds;
    }
}

// ==================== 4) node MLP (+ residual) ===========================
__global__ void __launch_bounds__(256) node_kernel(
    const float* __restrict__ feats,
    const float* __restrict__ Wn1, const float* __restrict__ bn1,
    const float* __restrict__ Wn2, const float* __restrict__ bn2,
    float* __restrict__ out)
{
    __shared__ float nin[8][192];
    __shared__ float hh [8][256];
    int n0 = blockIdx.x * 8;
    int t  = threadIdx.x;

    #pragma unroll
    for (int h = 0; h < 6; h++){
        int lin = t + h*256;
        int u = lin / 192, c = lin % 192;
        float v = (c < DD) ? feats[(size_t)(n0 + u)*DD + c]
                           : g_mi [(size_t)(n0 + u)*MD + (c - DD)];
        nin[u][c] = v;
    }
    __syncthreads();

    float a[8];
    #pragma unroll
    for (int u = 0; u < 8; u++) a[u] = bn1[t];
    for (int k = 0; k < 192; k++){
        float w = Wn1[(size_t)k*256 + t];
        #pragma unroll
        for (int u = 0; u < 8; u++) a[u] += nin[u][k]*w;
    }
    #pragma unroll
    for (int u = 0; u < 8; u++) hh[u][t] = silu_p(a[u]);
    __syncthreads();

    int col = t & 127, ug = t >> 7;
    float acc2[4];
    #pragma unroll
    for (int h = 0; h < 4; h++) acc2[h] = bn2[col];
    for (int k = 0; k < 256; k++){
        float w = Wn2[(size_t)k*DD + col];
        #pragma unroll
        for (int h = 0; h < 4; h++)
            acc2[h] += hh[ug + 2*h][k] * w;
    }
    #pragma unroll
    for (int h = 0; h < 4; h++){
        int u = ug + 2*h;
        out[(size_t)(n0 + u)*DD + col] =
            acc2[h] + feats[(size_t)(n0 + u)*DD + col];
    }
}

// ============================ launch =====================================
extern "C" void kernel_launch(void* const* d_in, const int* in_sizes, int n_in,
                              void* d_out, int out_size)
{
    (void)in_sizes; (void)n_in; (void)out_size;
    const float* feats = (const float*)d_in[0];
    const float* coors = (const float*)d_in[1];
    const float* We1   = (const float*)d_in[2];
    const float* be1   = (const float*)d_in[3];
    const float* We2   = (const float*)d_in[4];
    const float* be2   = (const float*)d_in[5];
    const float* Wc1   = (const float*)d_in[6];
    const float* bc1   = (const float*)d_in[7];
    const float* Wc2   = (const float*)d_in[8];
    const float* bc2   = (const float*)d_in[9];
    const float* Wn1   = (const float*)d_in[10];
    const float* bn1   = (const float*)d_in[11];
    const float* Wn2   = (const float*)d_in[12];
    const float* bn2   = (const float*)d_in[13];

    float* node_out  = (float*)d_out;
    float* coors_out = node_out + (size_t)NNODES*DD;

    prep_kernel<<<64, 256>>>(We1, be1, We2, Wc1);
    topk_kernel<<<NNODES, 256>>>(coors);
    pq_hmma<<<dim3(9, 64, 2), 256>>>(feats);
    edge_kernel<<<NNODES/4, 256>>>(coors, be2, bc1, Wc2, bc2, coors_out);
    node_kernel<<<NNODES/8, 256>>>(feats, Wn1, bn1, Wn2, bn2, node_out);
}

// round 17
// speedup vs baseline: 1.2687x; 1.2292x over previous
#include <cuda_runtime.h>
#include <cuda_bf16.h>
#include <math.h>
#include <stdint.h>

#define BB    4
#define NPTS  2048
#define DD    128
#define KNB   32
#define MD    64
#define H1P   576
#define H1W   288
#define H1R   530
#define NNODES (BB*NPTS)
#define NEDGES (NNODES*KNB)

// ---------------- device scratch ----------------
__device__ int   g_idx [NEDGES];
__device__ float g_relc[NEDGES*3];
__device__ float g_reld[NEDGES];
__device__ uint32_t g_Pb[(size_t)NNODES*H1W];
__device__ uint32_t g_Qb[(size_t)NNODES*H1W];
__device__ float g_mi  [(size_t)NNODES*MD];
__device__ uint32_t g_We2T[64*288];
__device__ uint32_t g_Wc1T[256*32];
__device__ uint32_t g_We1Ta[576*64];
__device__ uint32_t g_We1Tb[576*64];
__device__ uint32_t g_RWb[9*288];
__device__ uint32_t g_B1b[288];

__device__ __forceinline__ float silu_p(float x){
    float t = fminf(fmaxf(x, -2.f), 2.f);
    float u = t*t;
    float p = fmaf(u, -2.10813e-4f, 2.0833333e-3f);
    p = fmaf(u, p, -2.0833333e-2f);
    p = fmaf(u, p, 2.5e-1f);
    return x * fmaf(t, p, 0.5f);
}
__device__ __forceinline__ uint32_t silu2(__nv_bfloat162 x){
    __nv_bfloat162 hi = __float2bfloat162_rn(2.f);
    __nv_bfloat162 lo = __float2bfloat162_rn(-2.f);
    __nv_bfloat162 t = __hmin2(__hmax2(x, lo), hi);
    __nv_bfloat162 u = __hmul2(t, t);
    __nv_bfloat162 p = __hfma2(u, __float2bfloat162_rn(-2.10813e-4f),
                                  __float2bfloat162_rn(2.0833333e-3f));
    p = __hfma2(u, p, __float2bfloat162_rn(-2.0833333e-2f));
    p = __hfma2(u, p, __float2bfloat162_rn(2.5e-1f));
    __nv_bfloat162 s = __hfma2(t, p, __float2bfloat162_rn(0.5f));
    __nv_bfloat162 r = __hmul2(x, s);
    return *(uint32_t*)&r;
}
__device__ __forceinline__ unsigned long long umin64(unsigned long long a,
                                                     unsigned long long b){
    return a < b ? a : b;
}
__device__ __forceinline__ uint32_t smem_u32(const void* p){
    uint32_t a;
    asm("{ .reg .u64 t; cvta.to.shared.u64 t, %1; cvt.u32.u64 %0, t; }"
        : "=r"(a) : "l"(p));
    return a;
}
__device__ __forceinline__ void ldm_x4(uint32_t& r0, uint32_t& r1,
                                       uint32_t& r2, uint32_t& r3, uint32_t a){
    asm volatile("ldmatrix.sync.aligned.m8n8.x4.shared.b16 {%0,%1,%2,%3}, [%4];"
        : "=r"(r0), "=r"(r1), "=r"(r2), "=r"(r3) : "r"(a));
}
__device__ __forceinline__ void ldm_x2(uint32_t& r0, uint32_t& r1, uint32_t a){
    asm volatile("ldmatrix.sync.aligned.m8n8.x2.shared.b16 {%0,%1}, [%2];"
        : "=r"(r0), "=r"(r1) : "r"(a));
}

// ================ 0) prep: transposed/packed bf16 weights ================
__global__ void prep_kernel(const float* __restrict__ We1,
                            const float* __restrict__ be1,
                            const float* __restrict__ We2,
                            const float* __restrict__ Wc1)
{
    int t = blockIdx.x*256 + threadIdx.x;
    int stride = gridDim.x*256;
    for (int i = t; i < 64*288; i += stride){
        int k2 = i >> 6, n = i & 63;
        int r0 = 2*k2;
        float v0 = (r0     < H1R) ? We2[(size_t)r0*MD + n]     : 0.f;
        float v1 = (r0 + 1 < H1R) ? We2[(size_t)(r0+1)*MD + n] : 0.f;
        __nv_bfloat162 p = __floats2bfloat162_rn(v0, v1);
        g_We2T[n*288 + k2] = *(uint32_t*)&p;
    }
    for (int i = t; i < 256*32; i += stride){
        int k2 = i >> 8, n = i & 255;
        float v0 = Wc1[(size_t)(2*k2)*256 + n];
        float v1 = Wc1[(size_t)(2*k2+1)*256 + n];
        __nv_bfloat162 p = __floats2bfloat162_rn(v0, v1);
        g_Wc1T[n*32 + k2] = *(uint32_t*)&p;
    }
    for (int i = t; i < 64*576; i += stride){
        int w = i / 576, n = i % 576;
        float a0 = 0.f, a1 = 0.f, b0 = 0.f, b1 = 0.f;
        if (n < H1R){
            a0 = We1[(size_t)(2*w)*H1R + n];
            a1 = We1[(size_t)(2*w+1)*H1R + n];
            b0 = We1[(size_t)(128+2*w)*H1R + n];
            b1 = We1[(size_t)(128+2*w+1)*H1R + n];
        }
        __nv_bfloat162 pa = __floats2bfloat162_rn(a0, a1);
        __nv_bfloat162 pb = __floats2bfloat162_rn(b0, b1);
        g_We1Ta[n*64 + w] = *(uint32_t*)&pa;
        g_We1Tb[n*64 + w] = *(uint32_t*)&pb;
    }
    for (int i = t; i < 9*288; i += stride){
        int s = i / 288, w = i % 288;
        int gc = 2*w;
        float v0 = (gc     < H1R) ? We1[(size_t)(256+s)*H1R + gc]     : 0.f;
        float v1 = (gc + 1 < H1R) ? We1[(size_t)(256+s)*H1R + gc + 1] : 0.f;
        __nv_bfloat162 p = __floats2bfloat162_rn(v0, v1);
        g_RWb[i] = *(uint32_t*)&p;
    }
    for (int i = t; i < 288; i += stride){
        int gc = 2*i;
        float v0 = (gc     < H1R) ? be1[gc]     : 0.f;
        float v1 = (gc + 1 < H1R) ? be1[gc + 1] : 0.f;
        __nv_bfloat162 p = __floats2bfloat162_rn(v0, v1);
        g_B1b[i] = *(uint32_t*)&p;
    }
}

// ======== 1) kNN top-32 per node: lazy per-warp rescan ===================
// Warp w owns points [w*256, (w+1)*256). Per-warp min cached in cand[w];
// each round only the warp owning the removed point rescans.
__device__ __forceinline__ unsigned long long warp_seg_min(
    const float* dist, int w, int lid)
{
    unsigned long long best = 0xFFFFFFFFFFFFFFFFull;
    int base = w*256 + lid;
    #pragma unroll
    for (int r = 0; r < 8; r++){
        int j = base + r*32;
        unsigned int fb = __float_as_uint(dist[j]);
        unsigned long long key = ((unsigned long long)fb << 32) | (unsigned)j;
        best = umin64(best, key);
    }
    #pragma unroll
    for (int o = 16; o > 0; o >>= 1)
        best = umin64(best, __shfl_xor_sync(0xffffffffu, best, o));
    return best;
}

__global__ void __launch_bounds__(256) topk_kernel(const float* __restrict__ coors)
{
    __shared__ float dist[NPTS];
    __shared__ unsigned long long cand[8];
    __shared__ int   sOwner;
    __shared__ int   selj[KNB];
    __shared__ float seld[KNB];

    int row = blockIdx.x;
    int b   = row / NPTS;
    int t   = threadIdx.x;
    int wid = t >> 5, lid = t & 31;
    const float* cb = coors + (size_t)b*NPTS*3;
    float cx = coors[(size_t)row*3+0];
    float cy = coors[(size_t)row*3+1];
    float cz = coors[(size_t)row*3+2];

    for (int j = t; j < NPTS; j += 256){
        float dx = cx - cb[j*3+0];
        float dy = cy - cb[j*3+1];
        float dz = cz - cb[j*3+2];
        dist[j] = dx*dx + dy*dy + dz*dz;
    }
    __syncthreads();

    // initial per-warp minima
    {
        unsigned long long m = warp_seg_min(dist, wid, lid);
        if (lid == 0) cand[wid] = m;
    }
    __syncthreads();

    for (int kk = 0; kk < KNB; kk++){
        if (t == 0){
            unsigned long long m = cand[0];
            #pragma unroll
            for (int w = 1; w < 8; w++) m = umin64(m, cand[w]);
            int j = (int)(m & 0xFFFFFFFFull);
            selj[kk] = j;
            seld[kk] = __uint_as_float((unsigned)(m >> 32));
            dist[j]  = __uint_as_float(0x7F800000u);
            sOwner   = j >> 8;
        }
        __syncthreads();
        if (wid == sOwner){
            unsigned long long m = warp_seg_min(dist, wid, lid);
            if (lid == 0) cand[wid] = m;
        }
        __syncthreads();
    }

    if (t < KNB){
        int j = selj[t];
        size_t e = (size_t)row*KNB + t;
        g_idx [e] = j;
        g_reld[e] = seld[t];
        g_relc[e*3+0] = cx - cb[j*3+0];
        g_relc[e*3+1] = cy - cb[j*3+1];
        g_relc[e*3+2] = cz - cb[j*3+2];
    }
}

// ===== 2) P/Q via bf16 HMMA =============================================
__global__ void __launch_bounds__(256) pq_hmma(const float* __restrict__ feats)
{
    __shared__ uint32_t sA[128*36];
    __shared__ uint32_t sB[64*36];

    int which = blockIdx.z;
    uint32_t* C = which ? g_Qb : g_Pb;
    const uint32_t* WT = which ? g_We1Tb : g_We1Ta;
    int bn = blockIdx.x, bm = blockIdx.y;
    int t = threadIdx.x;
    int wid = t >> 5, lid = t & 31;
    int lr = lid >> 2, lc = lid & 3;
    int g8 = lid >> 3, l8 = lid & 7;

    uint32_t aBase = smem_u32(sA) +
        (((wid*16 + (g8 & 1)*8 + l8)*36 + (g8 >> 1)*4) << 2);
    uint32_t bBase = smem_u32(sB) + ((l8*36 + (g8 & 1)*4) << 2);

    float dacc[8][4];
    #pragma unroll
    for (int ni = 0; ni < 8; ni++)
        #pragma unroll
        for (int r = 0; r < 4; r++) dacc[ni][r] = 0.f;

    for (int ck = 0; ck < 2; ck++){
        #pragma unroll
        for (int it = 0; it < 8; it++){
            int lin = t + it*256;
            int rowi = lin >> 4;
            int f4  = lin & 15;
            float4 v = *(const float4*)(feats +
                (size_t)(bm*128 + rowi)*DD + ck*64 + f4*4);
            __nv_bfloat162 w0 = __floats2bfloat162_rn(v.x, v.y);
            __nv_bfloat162 w1 = __floats2bfloat162_rn(v.z, v.w);
            uint2 pk = make_uint2(*(uint32_t*)&w0, *(uint32_t*)&w1);
            *(uint2*)&sA[rowi*36 + f4*2] = pk;
        }
        #pragma unroll
        for (int h = 0; h < 2; h++){
            int lin = t + h*256;
            int n  = lin >> 3;
            int u4 = lin & 7;
            uint4 v = *(const uint4*)&WT[(size_t)(bn*64 + n)*64 + ck*32 + u4*4];
            *(uint4*)&sB[n*36 + u4*4] = v;
        }
        __syncthreads();

        #pragma unroll
        for (int ks = 0; ks < 4; ks++){
            uint32_t a0, a1, a2, a3;
            ldm_x4(a0, a1, a2, a3, aBase + ks*32);
            #pragma unroll
            for (int ni = 0; ni < 8; ni++){
                uint32_t b0, b1;
                ldm_x2(b0, b1, bBase + ni*1152 + ks*32);
                float* d = dacc[ni];
                asm volatile(
                    "mma.sync.aligned.m16n8k16.row.col.f32.bf16.bf16.f32 "
                    "{%0,%1,%2,%3}, {%4,%5,%6,%7}, {%8,%9}, {%0,%1,%2,%3};"
                    : "+f"(d[0]), "+f"(d[1]), "+f"(d[2]), "+f"(d[3])
                    : "r"(a0), "r"(a1), "r"(a2), "r"(a3),
                      "r"(b0), "r"(b1));
            }
        }
        __syncthreads();
    }

    int r0 = bm*128 + wid*16 + lr;
    #pragma unroll
    for (int ni = 0; ni < 8; ni++){
        float* d = dacc[ni];
        __nv_bfloat162 w0 = __floats2bfloat162_rn(d[0], d[1]);
        __nv_bfloat162 w1 = __floats2bfloat162_rn(d[2], d[3]);
        C[(size_t)r0*H1W     + bn*32 + ni*4 + lc] = *(uint32_t*)&w0;
        C[(size_t)(r0+8)*H1W + bn*32 + ni*4 + lc] = *(uint32_t*)&w1;
    }
}

// ==================== 3) fused edge pipeline (all-HMMA, ldmatrix) ========
#define U_SIZE 9472

__global__ void __launch_bounds__(256,3) edge_kernel(
    const float* __restrict__ coors,
    const float* __restrict__ be2,
    const float* __restrict__ bc1,
    const float* __restrict__ Wc2, const float* __restrict__ bc2,
    float* __restrict__ coors_out)
{
    __shared__ float smU[U_SIZE];
    __shared__ uint32_t sRD[128*10];
    __shared__ int   sIdx[128];
    __shared__ float sBe2[64];

    uint32_t* sA32 = (uint32_t*)smU;
    uint32_t* sB32 = (uint32_t*)(smU + 4608);
    uint32_t* sRWb = (uint32_t*)(smU + 6912);
    uint32_t* sB1b = (uint32_t*)(smU + 7200);
    uint32_t* sMb = sA32;
    uint32_t* sWb = sB32;
    float* sBc1 = smU + 9216;
    float* sWc2 = smU + 9344;
    float* sCw  = (float*)sRD;

    int t   = threadIdx.x;
    int wid = t >> 5;
    int lid = t & 31;
    int node0 = blockIdx.x * 4;
    int b = node0 / NPTS;
    int lr = lid >> 2, lc = lid & 3;
    int g8 = lid >> 3, l8 = lid & 7;

    uint32_t aBase = smem_u32(sA32) +
        (((wid*16 + (g8 & 1)*8 + l8)*36 + (g8 >> 1)*4) << 2);
    uint32_t bBase = smem_u32(sB32) + ((l8*36 + (g8 & 1)*4) << 2);

    if (t < 128){
        int e = t;
        sIdx[e] = g_idx[(size_t)node0*KNB + e];
        float d = g_reld[(size_t)node0*KNB + e];
        float fr[9];
        fr[8] = d;
        float x = d;
        #pragma unroll
        for (int s = 0; s < 4; s++){
            fr[s]     = sinf(x);
            fr[4 + s] = cosf(x);
            x *= 0.5f;
        }
        uint32_t* rb = &sRD[e*10];
        #pragma unroll
        for (int s = 0; s < 9; s++){
            uint16_t us = __bfloat16_as_ushort(__float2bfloat16(fr[s]));
            rb[s] = (uint32_t)us | ((uint32_t)us << 16);
        }
    }
    if (t < 64) sBe2[t] = be2[t];

    float dacc[8][4];
    #pragma unroll
    for (int ni = 0; ni < 8; ni++)
        #pragma unroll
        for (int r = 0; r < 4; r++) dacc[ni][r] = 0.f;

    for (int chunk = 0; chunk < 9; chunk++){
        int c0w = chunk*32;

        for (int lin = t; lin < 288; lin += 256){
            int s = lin >> 5, w = lin & 31;
            sRWb[s*32 + w] = g_RWb[s*288 + c0w + w];
        }
        if (t < 32) sB1b[t] = g_B1b[c0w + t];
        #pragma unroll
        for (int h = 0; h < 2; h++){
            int lin = t + h*256;
            int n  = lin >> 3;
            int u4 = lin & 7;
            uint4 v = *(const uint4*)&g_We2T[n*288 + c0w + u4*4];
            *(uint4*)&sB32[n*36 + u4*4] = v;
        }
        __syncthreads();

        #pragma unroll
        for (int it = 0; it < 4; it++){
            int lin = t + it*256;
            int e  = lin >> 3;
            int w4 = (lin & 7) * 4;
            int gi = node0 + (e >> 5);
            uint4 pw = *(const uint4*)&g_Pb[(size_t)gi*H1W + c0w + w4];
            uint4 qw = *(const uint4*)&g_Qb[(size_t)(b*NPTS + sIdx[e])*H1W + c0w + w4];
            uint4 bw = *(const uint4*)&sB1b[w4];
            __nv_bfloat162 h0 = __hadd2(__hadd2(*(__nv_bfloat162*)&pw.x,
                                                *(__nv_bfloat162*)&qw.x),
                                        *(__nv_bfloat162*)&bw.x);
            __nv_bfloat162 h1 = __hadd2(__hadd2(*(__nv_bfloat162*)&pw.y,
                                                *(__nv_bfloat162*)&qw.y),
                                        *(__nv_bfloat162*)&bw.y);
            __nv_bfloat162 h2 = __hadd2(__hadd2(*(__nv_bfloat162*)&pw.z,
                                                *(__nv_bfloat162*)&qw.z),
                                        *(__nv_bfloat162*)&bw.z);
            __nv_bfloat162 h3 = __hadd2(__hadd2(*(__nv_bfloat162*)&pw.w,
                                                *(__nv_bfloat162*)&qw.w),
                                        *(__nv_bfloat162*)&bw.w);
            const uint32_t* rb = &sRD[e*10];
            #pragma unroll
            for (int s = 0; s < 9; s++){
                uint32_t rvw = rb[s];
                __nv_bfloat162 rv = *(__nv_bfloat162*)&rvw;
                uint4 ww = *(const uint4*)&sRWb[s*32 + w4];
                h0 = __hfma2(rv, *(__nv_bfloat162*)&ww.x, h0);
                h1 = __hfma2(rv, *(__nv_bfloat162*)&ww.y, h1);
                h2 = __hfma2(rv, *(__nv_bfloat162*)&ww.z, h2);
                h3 = __hfma2(rv, *(__nv_bfloat162*)&ww.w, h3);
            }
            uint4 outw = make_uint4(silu2(h0), silu2(h1), silu2(h2), silu2(h3));
            *(uint4*)&sA32[e*36 + w4] = outw;
        }
        __syncthreads();

        #pragma unroll
        for (int ks = 0; ks < 4; ks++){
            uint32_t a0, a1, a2, a3;
            ldm_x4(a0, a1, a2, a3, aBase + ks*32);
            #pragma unroll
            for (int ni = 0; ni < 8; ni++){
                uint32_t b0, b1;
                ldm_x2(b0, b1, bBase + ni*1152 + ks*32);
                float* d = dacc[ni];
                asm volatile(
                    "mma.sync.aligned.m16n8k16.row.col.f32.bf16.bf16.f32 "
                    "{%0,%1,%2,%3}, {%4,%5,%6,%7}, {%8,%9}, {%0,%1,%2,%3};"
                    : "+f"(d[0]), "+f"(d[1]), "+f"(d[2]), "+f"(d[3])
                    : "r"(a0), "r"(a1), "r"(a2), "r"(a3),
                      "r"(b0), "r"(b1));
            }
        }
        __syncthreads();
    }

    {
        int r0 = wid*16 + lr;
        #pragma unroll
        for (int ni = 0; ni < 8; ni++){
            int c = ni*8 + lc*2;
            float b0v = sBe2[c], b1v = sBe2[c+1];
            float* d = dacc[ni];
            __nv_bfloat162 m0 = __floats2bfloat162_rn(silu_p(d[0]+b0v), silu_p(d[1]+b1v));
            __nv_bfloat162 m1 = __floats2bfloat162_rn(silu_p(d[2]+b0v), silu_p(d[3]+b1v));
            sMb[r0*36 + ni*4 + lc]     = *(uint32_t*)&m0;
            sMb[(r0+8)*36 + ni*4 + lc] = *(uint32_t*)&m1;
        }
    }
    __syncthreads();

    if (t < 128){
        int ni2 = t >> 5;
        int wq  = t & 31;
        float s0 = 0.f, s1 = 0.f;
        #pragma unroll 8
        for (int kk = 0; kk < 32; kk++){
            uint32_t w = sMb[(ni2*32 + kk)*36 + wq];
            __nv_bfloat162 h2 = *(__nv_bfloat162*)&w;
            s0 += __bfloat162float(__low2bfloat16(h2));
            s1 += __bfloat162float(__high2bfloat16(h2));
        }
        g_mi[(size_t)(node0 + ni2)*MD + 2*wq]     = s0;
        g_mi[(size_t)(node0 + ni2)*MD + 2*wq + 1] = s1;
    }

    uint32_t af[4][4];
    #pragma unroll
    for (int ks = 0; ks < 4; ks++)
        ldm_x4(af[ks][0], af[ks][1], af[ks][2], af[ks][3], aBase + ks*32);

    float cw0 = 0.f, cw1 = 0.f;
    for (int hf = 0; hf < 2; hf++){
        __syncthreads();
        #pragma unroll
        for (int h = 0; h < 4; h++){
            int lin = t + h*256;
            int n  = lin >> 3;
            int u4 = lin & 7;
            uint4 v = *(const uint4*)&g_Wc1T[(hf*128 + n)*32 + u4*4];
            *(uint4*)&sWb[n*36 + u4*4] = v;
        }
        if (t < 128) sBc1[t] = bc1[hf*128 + t];
        else         sWc2[t-128] = Wc2[hf*128 + (t-128)];
        __syncthreads();
        #pragma unroll
        for (int ni = 0; ni < 16; ni++){
            float d0 = 0.f, d1 = 0.f, d2 = 0.f, d3 = 0.f;
            #pragma unroll
            for (int ks = 0; ks < 4; ks++){
                uint32_t b0, b1;
                ldm_x2(b0, b1, bBase + ni*1152 + ks*32);
                asm volatile(
                    "mma.sync.aligned.m16n8k16.row.col.f32.bf16.bf16.f32 "
                    "{%0,%1,%2,%3}, {%4,%5,%6,%7}, {%8,%9}, {%0,%1,%2,%3};"
                    : "+f"(d0), "+f"(d1), "+f"(d2), "+f"(d3)
                    : "r"(af[ks][0]), "r"(af[ks][1]),
                      "r"(af[ks][2]), "r"(af[ks][3]),
                      "r"(b0), "r"(b1));
            }
            int cl = ni*8 + lc*2;
            float bb0 = sBc1[cl], bb1 = sBc1[cl+1];
            float w0 = sWc2[cl],  w1 = sWc2[cl+1];
            cw0 += silu_p(d0 + bb0)*w0 + silu_p(d1 + bb1)*w1;
            cw1 += silu_p(d2 + bb0)*w0 + silu_p(d3 + bb1)*w1;
        }
    }
    cw0 += __shfl_xor_sync(0xffffffffu, cw0, 1);
    cw0 += __shfl_xor_sync(0xffffffffu, cw0, 2);
    cw1 += __shfl_xor_sync(0xffffffffu, cw1, 1);
    cw1 += __shfl_xor_sync(0xffffffffu, cw1, 2);
    __syncthreads();
    if (lc == 0){
        sCw[wid*16 + lr]     = cw0;
        sCw[wid*16 + lr + 8] = cw1;
    }
    __syncthreads();

    if (t < 12){
        int ni = t / 3, dim = t % 3;
        float bc2v = bc2[0];
        float ds = 0.f;
        for (int kk = 0; kk < 32; kk++){
            int e = ni*32 + kk;
            float cwv = sCw[e] + bc2v;
            ds += cwv * g_relc[((size_t)(node0 + ni)*KNB + kk)*3 + dim];
        }
        coors_out[(size_t)(node0 + ni)*3 + dim] =
            coors[(size_t)(node0 + ni)*3 + dim] + ds;
    }
}

// ==================== 4) node MLP (+ residual) ===========================
__global__ void __launch_bounds__(256) node_kernel(
    const float* __restrict__ feats,
    const float* __restrict__ Wn1, const float* __restrict__ bn1,
    const float* __restrict__ Wn2, const float* __restrict__ bn2,
    float* __restrict__ out)
{
    __shared__ float nin[8][192];
    __shared__ float hh [8][256];
    int n0 = blockIdx.x * 8;
    int t  = threadIdx.x;

    #pragma unroll
    for (int h = 0; h < 6; h++){
        int lin = t + h*256;
        int u = lin / 192, c = lin % 192;
        float v = (c < DD) ? feats[(size_t)(n0 + u)*DD + c]
                           : g_mi [(size_t)(n0 + u)*MD + (c - DD)];
        nin[u][c] = v;
    }
    __syncthreads();

    float a[8];
    #pragma unroll
    for (int u = 0; u < 8; u++) a[u] = bn1[t];
    for (int k = 0; k < 192; k++){
        float w = Wn1[(size_t)k*256 + t];
        #pragma unroll
        for (int u = 0; u < 8; u++) a[u] += nin[u][k]*w;
    }
    #pragma unroll
    for (int u = 0; u < 8; u++) hh[u][t] = silu_p(a[u]);
    __syncthreads();

    int col = t & 127, ug = t >> 7;
    float acc2[4];
    #pragma unroll
    for (int h = 0; h < 4; h++) acc2[h] = bn2[col];
    for (int k = 0; k < 256; k++){
        float w = Wn2[(size_t)k*DD + col];
        #pragma unroll
        for (int h = 0; h < 4; h++)
            acc2[h] += hh[ug + 2*h][k] * w;
    }
    #pragma unroll
    for (int h = 0; h < 4; h++){
        int u = ug + 2*h;
        out[(size_t)(n0 + u)*DD + col] =
            acc2[h] + feats[(size_t)(n0 + u)*DD + col];
    }
}

// ============================ launch =====================================
extern "C" void kernel_launch(void* const* d_in, const int* in_sizes, int n_in,
                              void* d_out, int out_size)
{
    (void)in_sizes; (void)n_in; (void)out_size;
    const float* feats = (const float*)d_in[0];
    const float* coors = (const float*)d_in[1];
    const float* We1   = (const float*)d_in[2];
    const float* be1   = (const float*)d_in[3];
    const float* We2   = (const float*)d_in[4];
    const float* be2   = (const float*)d_in[5];
    const float* Wc1   = (const float*)d_in[6];
    const float* bc1   = (const float*)d_in[7];
    const float* Wc2   = (const float*)d_in[8];
    const float* bc2   = (const float*)d_in[9];
    const float* Wn1   = (const float*)d_in[10];
    const float* bn1   = (const float*)d_in[11];
    const float* Wn2   = (const float*)d_in[12];
    const float* bn2   = (const float*)d_in[13];

    float* node_out  = (float*)d_out;
    float* coors_out = node_out + (size_t)NNODES*DD;

    prep_kernel<<<64, 256>>>(We1, be1, We2, Wc1);
    topk_kernel<<<NNODES, 256>>>(coors);
    pq_hmma<<<dim3(9, 64, 2), 256>>>(feats);
    edge_kernel<<<NNODES/4, 256>>>(coors, be2, bc1, Wc2, bc2, coors_out);
    node_kernel<<<NNODES/8, 256>>>(feats, Wn1, bn1, Wn2, bn2, node_out);
}